// round 8
// baseline (speedup 1.0000x reference)
#include <cuda_runtime.h>
#include <cstdint>

#define NN 50000
#define EE 800000
#define HH 128
#define RR 8

// ---------------- scratch (device globals; no allocation allowed) ----------------
__device__ float g_agg[(size_t)RR * NN * HH];  // [rel][N][128] per-relation neighbor means
__device__ float g_hA[(size_t)NN * HH];
__device__ float g_hB[(size_t)NN * HH];
__device__ int   g_cnt[NN * RR];
__device__ float g_invc[NN * RR];
__device__ int   g_rowptr[NN + 1];
__device__ int   g_beg[NN * RR];
__device__ int   g_cur[NN * RR];
__device__ int   g_ep[EE];            // src node id, CSR-sorted by (dst, etype)
__device__ float g_m[9 * HH];         // column sums: slots 0..7 = g_agg[r], 8 = last hidden
__device__ float g_u[2 * HH];         // final per-graph embeddings

// ---------------- tf32 mma (raw fp32 bits; HW uses top 19 bits = RZ-truncated tf32)
__device__ __forceinline__ void mma_tf32(float* c, const unsigned* a, const unsigned* b) {
    asm volatile(
        "mma.sync.aligned.m16n8k8.row.col.f32.tf32.tf32.f32 "
        "{%0,%1,%2,%3}, {%4,%5,%6,%7}, {%8,%9}, {%0,%1,%2,%3};"
        : "+f"(c[0]), "+f"(c[1]), "+f"(c[2]), "+f"(c[3])
        : "r"(a[0]), "r"(a[1]), "r"(a[2]), "r"(a[3]), "r"(b[0]), "r"(b[1]));
}

// ---------------- zero init ----------------
__global__ void zero_kernel() {
    int i = blockIdx.x * blockDim.x + threadIdx.x;
    if (i < NN * RR) g_cnt[i] = 0;
    if (i < 9 * HH) g_m[i] = 0.f;
}

// ---------------- graph preprocessing ----------------
__global__ void hist_kernel(const int* __restrict__ ei, const int* __restrict__ et) {
    int e = blockIdx.x * blockDim.x + threadIdx.x;
    if (e < EE) {
        int dst = ei[EE + e];
        int r = et[e];
        atomicAdd(&g_cnt[dst * RR + r], 1);
    }
}

// single-block scan over node degrees + per-(node,rel) segment expansion
__global__ void scanexp_kernel() {
    __shared__ int sh[1024];
    __shared__ int s_carry;
    int tid = threadIdx.x;
    if (tid == 0) { s_carry = 0; g_rowptr[0] = 0; }
    __syncthreads();
    for (int base = 0; base < NN; base += 1024) {
        int i = base + tid;
        int cv[RR];
        int v = 0;
        if (i < NN) {
            #pragma unroll
            for (int r = 0; r < RR; r++) { cv[r] = g_cnt[i * RR + r]; v += cv[r]; }
        }
        sh[tid] = v;
        __syncthreads();
        for (int off = 1; off < 1024; off <<= 1) {
            int t = (tid >= off) ? sh[tid - off] : 0;
            __syncthreads();
            sh[tid] += t;
            __syncthreads();
        }
        int incl = sh[tid];
        int c = s_carry;
        if (i < NN) {
            g_rowptr[i + 1] = c + incl;
            int c0 = c + incl - v;            // = rowptr[i]
            #pragma unroll
            for (int r = 0; r < RR; r++) {
                g_beg[i * RR + r] = c0;
                g_cur[i * RR + r] = c0;
                g_invc[i * RR + r] = 1.0f / (float)(cv[r] > 0 ? cv[r] : 1);
                c0 += cv[r];
            }
        }
        __syncthreads();
        if (tid == 0) s_carry = c + sh[1023];
        __syncthreads();
    }
}

__global__ void scatter_kernel(const int* __restrict__ ei, const int* __restrict__ et) {
    int e = blockIdx.x * blockDim.x + threadIdx.x;
    if (e < EE) {
        int comb = ei[EE + e] * RR + et[e];
        int pos = atomicAdd(&g_cur[comb], 1);
        g_ep[pos] = ei[e];
    }
}

// ---------------- aggregation: warp per (rel,node); writes g_agg[rel][N][128] -----
__global__ void agg_kernel(const float* __restrict__ X) {
    int gw = (blockIdx.x * blockDim.x + threadIdx.x) >> 5;
    int lane = threadIdx.x & 31;
    if (gw >= NN * RR) return;
    int rel = gw / NN;
    int node = gw - rel * NN;

    int comb = node * RR + rel;
    int b = g_beg[comb];
    int c = g_cnt[comb];
    float4 a = make_float4(0.f, 0.f, 0.f, 0.f);
    for (int e = b; e < b + c; e++) {
        int src = g_ep[e];
        float4 v = ((const float4*)(X + (size_t)src * HH))[lane];
        a.x += v.x; a.y += v.y; a.z += v.z; a.w += v.w;
    }
    float w = g_invc[comb];
    a.x *= w; a.y *= w; a.z *= w; a.w *= w;
    ((float4*)(g_agg + ((size_t)rel * NN + node) * HH))[lane] = a;
}

// ---------------- tf32 tensor-core GEMM (layers 0,1) -----------------------------
// out[N,128] = relu( sum_r A_r @ W_r + X @ root + bias ); A_r = g_agg[r], K = 9*128.
// CTA: 128x128 tile, 256 threads = 8 warps (4x2), warp tile 32x64, m16n8k8, BK=32.
#define BM 128
#define GBLK ((NN + BM - 1) / BM)
#define APAD 36
#define BPAD 136

__global__ __launch_bounds__(256) void gemm_kernel(
    const float* __restrict__ X, const float* __restrict__ W,
    const float* __restrict__ root, const float* __restrict__ bias,
    float* __restrict__ out)
{
    __shared__ float As[128 * APAD];   // 128 rows x 32 k (raw fp32 bits)
    __shared__ float Bs[32 * BPAD];    // 32 k x 128 n (raw fp32 bits)

    int tid  = threadIdx.x;
    int warp = tid >> 5;
    int lane = tid & 31;
    int gID  = lane >> 2;              // 0..7
    int tig  = lane & 3;               // 0..3
    int wrow = (warp & 3) * 32;
    int wcol = (warp >> 2) * 64;
    int m0   = blockIdx.x * BM;

    float c[2][8][4];
    #pragma unroll
    for (int mt = 0; mt < 2; mt++)
        #pragma unroll
        for (int nt = 0; nt < 8; nt++)
            #pragma unroll
            for (int q = 0; q < 4; q++) c[mt][nt][q] = 0.f;

    for (int rel = 0; rel < 9; rel++) {
        const float* Wp   = (rel < RR) ? (W + (size_t)rel * HH * HH) : root;
        const float* Asrc = (rel < RR) ? (g_agg + (size_t)rel * NN * HH) : X;

        for (int kc = 0; kc < 4; kc++) {
            // stage A: 128 rows x 32 k (raw bits; mma truncates to tf32)
            #pragma unroll
            for (int it = 0; it < 4; it++) {
                int idx = tid + it * 256;          // 0..1023
                int row = idx >> 3;
                int q   = idx & 7;
                int gm  = m0 + row;
                float4 v = make_float4(0.f, 0.f, 0.f, 0.f);
                if (gm < NN)
                    v = *(const float4*)(Asrc + (size_t)gm * HH + kc * 32 + q * 4);
                *(float4*)(As + row * APAD + q * 4) = v;
            }
            // stage B: 32 k x 128 n
            #pragma unroll
            for (int it = 0; it < 4; it++) {
                int idx = tid + it * 256;          // 0..1023
                int kr = idx >> 5;
                int nq = (idx & 31) * 4;
                float4 w = *(const float4*)(Wp + (size_t)(kc * 32 + kr) * HH + nq);
                *(float4*)(Bs + kr * BPAD + nq) = w;
            }
            __syncthreads();

            #pragma unroll
            for (int ks = 0; ks < 4; ks++) {
                int kb = ks * 8;
                unsigned b[8][2];
                #pragma unroll
                for (int nt = 0; nt < 8; nt++) {
                    int col = wcol + nt * 8 + gID;
                    b[nt][0] = __float_as_uint(Bs[(kb + tig) * BPAD + col]);
                    b[nt][1] = __float_as_uint(Bs[(kb + tig + 4) * BPAD + col]);
                }
                unsigned a[2][4];
                #pragma unroll
                for (int mt = 0; mt < 2; mt++) {
                    int r = wrow + mt * 16 + gID;
                    a[mt][0] = __float_as_uint(As[r * APAD + kb + tig]);
                    a[mt][1] = __float_as_uint(As[(r + 8) * APAD + kb + tig]);
                    a[mt][2] = __float_as_uint(As[r * APAD + kb + tig + 4]);
                    a[mt][3] = __float_as_uint(As[(r + 8) * APAD + kb + tig + 4]);
                }
                #pragma unroll
                for (int mt = 0; mt < 2; mt++)
                    #pragma unroll
                    for (int nt = 0; nt < 8; nt++)
                        mma_tf32(c[mt][nt], a[mt], b[nt]);
            }
            __syncthreads();
        }
    }

    // epilogue: bias, relu, store
    #pragma unroll
    for (int mt = 0; mt < 2; mt++) {
        int r0 = m0 + wrow + mt * 16 + gID;
        int r1 = r0 + 8;
        #pragma unroll
        for (int nt = 0; nt < 8; nt++) {
            int col = wcol + nt * 8 + 2 * tig;
            float b0 = bias[col], b1 = bias[col + 1];
            float v0 = fmaxf(c[mt][nt][0] + b0, 0.f);
            float v1 = fmaxf(c[mt][nt][1] + b1, 0.f);
            float v2 = fmaxf(c[mt][nt][2] + b0, 0.f);
            float v3 = fmaxf(c[mt][nt][3] + b1, 0.f);
            if (r0 < NN) *(float2*)(out + (size_t)r0 * HH + col) = make_float2(v0, v1);
            if (r1 < NN) *(float2*)(out + (size_t)r1 * HH + col) = make_float2(v2, v3);
        }
    }
}

// ---------------- layer-3 collapse: column sums of g_agg slots + last hidden -----
__global__ void colmean_kernel(const float* __restrict__ Xlast) {
    int slot = blockIdx.y;             // 0..8
    const float* src = (slot < RR) ? (g_agg + (size_t)slot * NN * HH) : Xlast;
    __shared__ float sh[256];
    int tid = threadIdx.x;
    int col = tid & 127;
    int half = tid >> 7;
    int rowsPer = (NN + gridDim.x - 1) / gridDim.x;
    int r0 = blockIdx.x * rowsPer;
    int r1 = min(NN, r0 + rowsPer);
    float local = 0.f;
    for (int r = r0 + half; r < r1; r += 2)
        local += src[(size_t)r * HH + col];
    sh[tid] = local;
    __syncthreads();
    if (tid < 128) atomicAdd(&g_m[slot * HH + col], sh[tid] + sh[tid + 128]);
}

// ---------------- layer-3 GEMV: u = (1/N) * (sum_r m_r@W_r + mX@root) + bias ------
__global__ void gemv_kernel(const float* __restrict__ W, const float* __restrict__ root,
                            const float* __restrict__ bias, float* __restrict__ uo) {
    __shared__ float m[9 * HH];
    int tid = threadIdx.x;             // 128
    for (int i = tid; i < 9 * HH; i += 128) m[i] = g_m[i];
    __syncthreads();
    float acc = 0.f;
    for (int r = 0; r < RR; r++) {
        const float* Wr = W + (size_t)r * HH * HH;
        #pragma unroll 4
        for (int k = 0; k < HH; k++)
            acc += m[r * HH + k] * Wr[k * HH + tid];
    }
    #pragma unroll 4
    for (int k = 0; k < HH; k++)
        acc += m[8 * HH + k] * root[k * HH + tid];
    uo[tid] = acc * (1.0f / (float)NN) + bias[tid];
}

// ---------------- final MLP head (g_u already holds the means) ----------------
__global__ void fcl_kernel(const float* __restrict__ fc1w, const float* __restrict__ fc1b,
                           const float* __restrict__ fc2w, const float* __restrict__ fc2b,
                           float* __restrict__ out) {
    __shared__ float h[2 * HH];
    __shared__ float red[HH];
    int tid = threadIdx.x;
    if (tid < 2 * HH) h[tid] = g_u[tid];
    __syncthreads();
    if (tid < HH) {
        float y = fc1b[tid];
        for (int k = 0; k < 2 * HH; k++) y += h[k] * fc1w[k * HH + tid];
        y = fmaxf(y, 0.f);
        red[tid] = y * fc2w[tid];
    }
    __syncthreads();
    for (int off = 64; off > 0; off >>= 1) {
        if (tid < off) red[tid] += red[tid + off];
        __syncthreads();
    }
    if (tid == 0) out[0] = red[0] + fc2b[0];
}

// ---------------- host orchestration ----------------
extern "C" void kernel_launch(void* const* d_in, const int* in_sizes, int n_in,
                              void* d_out, int out_size) {
    const float* x1  = (const float*)d_in[0];
    const int*   ei1 = (const int*)d_in[1];
    const int*   et1 = (const int*)d_in[2];
    const float* x2  = (const float*)d_in[3];
    const int*   ei2 = (const int*)d_in[4];
    const int*   et2 = (const int*)d_in[5];
    const float* Wl[3]    = {(const float*)d_in[6],  (const float*)d_in[9],  (const float*)d_in[12]};
    const float* rootl[3] = {(const float*)d_in[7],  (const float*)d_in[10], (const float*)d_in[13]};
    const float* biasl[3] = {(const float*)d_in[8],  (const float*)d_in[11], (const float*)d_in[14]};
    const float* fc1w = (const float*)d_in[15];
    const float* fc1b = (const float*)d_in[16];
    const float* fc2w = (const float*)d_in[17];
    const float* fc2b = (const float*)d_in[18];

    void *u_p, *hA_p, *hB_p;
    cudaGetSymbolAddress(&u_p, g_u);
    cudaGetSymbolAddress(&hA_p, g_hA);
    cudaGetSymbolAddress(&hB_p, g_hB);
    float* hA = (float*)hA_p;
    float* hB = (float*)hB_p;
    float* u  = (float*)u_p;

    const float* xs[2]  = {x1, x2};
    const int*   eis[2] = {ei1, ei2};
    const int*   ets[2] = {et1, et2};

    int aggBlocks  = (NN * RR * 32 + 255) / 256;
    int zeroBlocks = (NN * RR + 255) / 256;
    dim3 cmGrid(64, 9);

    for (int g = 0; g < 2; g++) {
        zero_kernel<<<zeroBlocks, 256>>>();                          // cnt + m
        hist_kernel<<<(EE + 255) / 256, 256>>>(eis[g], ets[g]);
        scanexp_kernel<<<1, 1024>>>();
        scatter_kernel<<<(EE + 255) / 256, 256>>>(eis[g], ets[g]);

        // layer 0: x -> hA
        agg_kernel<<<aggBlocks, 256>>>(xs[g]);
        gemm_kernel<<<GBLK, 256>>>(xs[g], Wl[0], rootl[0], biasl[0], hA);
        // layer 1: hA -> hB
        agg_kernel<<<aggBlocks, 256>>>(hA);
        gemm_kernel<<<GBLK, 256>>>(hA, Wl[1], rootl[1], biasl[1], hB);
        // layer 2 collapsed: only column means are needed
        agg_kernel<<<aggBlocks, 256>>>(hB);
        colmean_kernel<<<cmGrid, 256>>>(hB);
        gemv_kernel<<<1, 128>>>(Wl[2], rootl[2], biasl[2], u + g * HH);
    }

    fcl_kernel<<<1, 256>>>(fc1w, fc1b, fc2w, fc2b, (float*)d_out);
}

// round 9
// speedup vs baseline: 2.3964x; 2.3964x over previous
#include <cuda_runtime.h>
#include <cstdint>

#define NN 50000
#define EE 800000
#define HH 128
#define RR 8
#define SNB 196                       // ceil(NN/256) node blocks

// ---------------- scratch (device globals; no allocation allowed) ----------------
__device__ float g_agg[(size_t)RR * NN * HH];  // [rel][N][128] per-relation neighbor means
__device__ float g_hA[(size_t)NN * HH];
__device__ float g_hB[(size_t)NN * HH];
__device__ int   g_cnt[NN * RR];
__device__ float g_invc[NN * RR];
__device__ int   g_beg[NN * RR];
__device__ int   g_cur[NN * RR];
__device__ int   g_bsum[SNB];         // edges per 256-node block
__device__ int   g_ep[EE];            // src node id, CSR-sorted by (dst, etype)
__device__ float g_m[9 * HH];         // column sums: slots 0..7 = g_agg[r], 8 = last hidden
__device__ float g_u[2 * HH];         // final per-graph embeddings (pre-bias)

// ---------------- tf32 mma (raw fp32 bits = RZ-truncated tf32) ----------------
__device__ __forceinline__ void mma_tf32(float* c, const unsigned* a, const unsigned* b) {
    asm volatile(
        "mma.sync.aligned.m16n8k8.row.col.f32.tf32.tf32.f32 "
        "{%0,%1,%2,%3}, {%4,%5,%6,%7}, {%8,%9}, {%0,%1,%2,%3};"
        : "+f"(c[0]), "+f"(c[1]), "+f"(c[2]), "+f"(c[3])
        : "r"(a[0]), "r"(a[1]), "r"(a[2]), "r"(a[3]), "r"(b[0]), "r"(b[1]));
}

// ---------------- cp.async helpers ----------------
__device__ __forceinline__ void cp16(uint32_t saddr, const void* gaddr) {
    asm volatile("cp.async.cg.shared.global [%0], [%1], 16;" :: "r"(saddr), "l"(gaddr));
}
__device__ __forceinline__ void cp_commit() {
    asm volatile("cp.async.commit_group;");
}
template <int N>
__device__ __forceinline__ void cp_wait() {
    asm volatile("cp.async.wait_group %0;" :: "n"(N));
}

// ---------------- preprocessing ----------------
__global__ void hist_kernel(const int* __restrict__ ei, const int* __restrict__ et) {
    int e = blockIdx.x * blockDim.x + threadIdx.x;
    if (e < EE) {
        int dst = ei[EE + e];
        int r = et[e];
        atomicAdd(&g_cnt[dst * RR + r], 1);
        atomicAdd(&g_bsum[dst >> 8], 1);
    }
}

// 196 blocks x 256: predecessor prefix over g_bsum + local node scan -> beg/cur/invc
__global__ void expand_kernel() {
    __shared__ int sh[256];
    __shared__ int s_base;
    int b = blockIdx.x;
    int tid = threadIdx.x;

    // prefix = sum of g_bsum[0..b-1]
    sh[tid] = (tid < b) ? g_bsum[tid] : 0;
    __syncthreads();
    for (int off = 128; off > 0; off >>= 1) {
        if (tid < off) sh[tid] += sh[tid + off];
        __syncthreads();
    }
    if (tid == 0) s_base = sh[0];
    __syncthreads();

    int i = b * 256 + tid;
    int cv[RR];
    int d = 0;
    if (i < NN) {
        int4 c0 = *(const int4*)&g_cnt[i * RR];
        int4 c1 = *(const int4*)&g_cnt[i * RR + 4];
        cv[0] = c0.x; cv[1] = c0.y; cv[2] = c0.z; cv[3] = c0.w;
        cv[4] = c1.x; cv[5] = c1.y; cv[6] = c1.z; cv[7] = c1.w;
        #pragma unroll
        for (int r = 0; r < RR; r++) d += cv[r];
    }
    sh[tid] = d;
    __syncthreads();
    for (int off = 1; off < 256; off <<= 1) {
        int t = (tid >= off) ? sh[tid - off] : 0;
        __syncthreads();
        sh[tid] += t;
        __syncthreads();
    }
    if (i < NN) {
        int c0 = s_base + sh[tid] - d;    // exclusive start for node i
        #pragma unroll
        for (int r = 0; r < RR; r++) {
            g_beg[i * RR + r] = c0;
            g_cur[i * RR + r] = c0;
            g_invc[i * RR + r] = 1.0f / (float)(cv[r] > 0 ? cv[r] : 1);
            c0 += cv[r];
        }
    }
}

__global__ void scatter_kernel(const int* __restrict__ ei, const int* __restrict__ et) {
    int e = blockIdx.x * blockDim.x + threadIdx.x;
    if (e < EE) {
        int comb = ei[EE + e] * RR + et[e];
        int pos = atomicAdd(&g_cur[comb], 1);
        g_ep[pos] = ei[e];
    }
}

// ---------------- aggregation: warp per (rel,node); writes g_agg[rel][N][128] -----
__global__ void agg_kernel(const float* __restrict__ X) {
    int gw = (blockIdx.x * blockDim.x + threadIdx.x) >> 5;
    int lane = threadIdx.x & 31;
    if (gw >= NN * RR) return;
    int rel = gw / NN;
    int node = gw - rel * NN;

    int comb = node * RR + rel;
    int b = g_beg[comb];
    int c = g_cnt[comb];
    float4 a = make_float4(0.f, 0.f, 0.f, 0.f);
    for (int e = b; e < b + c; e++) {
        int src = g_ep[e];
        float4 v = ((const float4*)(X + (size_t)src * HH))[lane];
        a.x += v.x; a.y += v.y; a.z += v.z; a.w += v.w;
    }
    float w = g_invc[comb];
    a.x *= w; a.y *= w; a.z *= w; a.w *= w;
    ((float4*)(g_agg + ((size_t)rel * NN + node) * HH))[lane] = a;
}

// ---------------- tf32 tensor-core GEMM, cp.async double-buffered -----------------
// out[N,128] = relu( sum_r A_r @ W_r + X @ root + bias ); K = 9*128 in 36 BK=32 chunks.
#define BM 128
#define GBLK ((NN + BM - 1) / BM)
#define APAD 36
#define BPAD 136
#define ASZ (128 * APAD)
#define BSZ (32 * BPAD)
#define GSMEM (2 * (ASZ + BSZ) * 4)

__global__ __launch_bounds__(256) void gemm_kernel(
    const float* __restrict__ X, const float* __restrict__ W,
    const float* __restrict__ root, const float* __restrict__ bias,
    float* __restrict__ out)
{
    extern __shared__ float smem[];
    // layout: As0 | As1 | Bs0 | Bs1
    uint32_t sbase = (uint32_t)__cvta_generic_to_shared(smem);

    int tid  = threadIdx.x;
    int warp = tid >> 5;
    int lane = tid & 31;
    int gID  = lane >> 2;
    int tig  = lane & 3;
    int wrow = (warp & 3) * 32;
    int wcol = (warp >> 2) * 64;
    int m0   = blockIdx.x * BM;

    // staging indices (constant per thread)
    int arow = tid >> 3, aq = (tid & 7) * 4;          // + it*32 rows
    int bkr  = tid >> 5, bnq = (tid & 31) * 4;        // + it*8 k-rows

    float c[2][8][4];
    #pragma unroll
    for (int mt = 0; mt < 2; mt++)
        #pragma unroll
        for (int nt = 0; nt < 8; nt++)
            #pragma unroll
            for (int q = 0; q < 4; q++) c[mt][nt][q] = 0.f;

    // stage chunk ch into buffer buf via cp.async
    auto stage = [&](int ch, int buf) {
        int rel = ch >> 2, kc = ch & 3;
        const float* Wp   = (rel < RR) ? (W + (size_t)rel * HH * HH) : root;
        const float* Asrc = (rel < RR) ? (g_agg + (size_t)rel * NN * HH) : X;
        uint32_t abase = sbase + (uint32_t)(buf * ASZ) * 4;
        uint32_t bbase = sbase + (uint32_t)(2 * ASZ + buf * BSZ) * 4;
        #pragma unroll
        for (int it = 0; it < 4; it++) {
            int row = arow + it * 32;
            int gm  = m0 + row; if (gm > NN - 1) gm = NN - 1;   // clamp; rows >= NN discarded
            cp16(abase + (uint32_t)(row * APAD + aq) * 4,
                 Asrc + (size_t)gm * HH + kc * 32 + aq);
            int kr = bkr + it * 8;
            cp16(bbase + (uint32_t)(kr * BPAD + bnq) * 4,
                 Wp + (size_t)(kc * 32 + kr) * HH + bnq);
        }
        cp_commit();
    };

    stage(0, 0);

    for (int ch = 0; ch < 36; ch++) {
        int buf = ch & 1;
        if (ch < 35) { stage(ch + 1, buf ^ 1); cp_wait<1>(); }
        else         { cp_wait<0>(); }
        __syncthreads();

        const float* As = smem + buf * ASZ;
        const float* Bs = smem + 2 * ASZ + buf * BSZ;

        #pragma unroll
        for (int ks = 0; ks < 4; ks++) {
            int kb = ks * 8;
            unsigned b[8][2];
            #pragma unroll
            for (int nt = 0; nt < 8; nt++) {
                int col = wcol + nt * 8 + gID;
                b[nt][0] = __float_as_uint(Bs[(kb + tig) * BPAD + col]);
                b[nt][1] = __float_as_uint(Bs[(kb + tig + 4) * BPAD + col]);
            }
            unsigned a[2][4];
            #pragma unroll
            for (int mt = 0; mt < 2; mt++) {
                int r = wrow + mt * 16 + gID;
                a[mt][0] = __float_as_uint(As[r * APAD + kb + tig]);
                a[mt][1] = __float_as_uint(As[(r + 8) * APAD + kb + tig]);
                a[mt][2] = __float_as_uint(As[r * APAD + kb + tig + 4]);
                a[mt][3] = __float_as_uint(As[(r + 8) * APAD + kb + tig + 4]);
            }
            #pragma unroll
            for (int mt = 0; mt < 2; mt++)
                #pragma unroll
                for (int nt = 0; nt < 8; nt++)
                    mma_tf32(c[mt][nt], a[mt], b[nt]);
        }
        __syncthreads();
    }

    // epilogue: bias, relu, store
    #pragma unroll
    for (int mt = 0; mt < 2; mt++) {
        int r0 = m0 + wrow + mt * 16 + gID;
        int r1 = r0 + 8;
        #pragma unroll
        for (int nt = 0; nt < 8; nt++) {
            int col = wcol + nt * 8 + 2 * tig;
            float b0 = bias[col], b1 = bias[col + 1];
            float v0 = fmaxf(c[mt][nt][0] + b0, 0.f);
            float v1 = fmaxf(c[mt][nt][1] + b1, 0.f);
            float v2 = fmaxf(c[mt][nt][2] + b0, 0.f);
            float v3 = fmaxf(c[mt][nt][3] + b1, 0.f);
            if (r0 < NN) *(float2*)(out + (size_t)r0 * HH + col) = make_float2(v0, v1);
            if (r1 < NN) *(float2*)(out + (size_t)r1 * HH + col) = make_float2(v2, v3);
        }
    }
}

// ---------------- layer-3 collapse: column sums of g_agg slots + last hidden -----
__global__ void colmean_kernel(const float* __restrict__ Xlast) {
    int slot = blockIdx.y;             // 0..8
    const float* src = (slot < RR) ? (g_agg + (size_t)slot * NN * HH) : Xlast;
    __shared__ float sh[256];
    int tid = threadIdx.x;
    int col = tid & 127;
    int half = tid >> 7;
    int rowsPer = (NN + gridDim.x - 1) / gridDim.x;
    int r0 = blockIdx.x * rowsPer;
    int r1 = min(NN, r0 + rowsPer);
    float local = 0.f;
    for (int r = r0 + half; r < r1; r += 2)
        local += src[(size_t)r * HH + col];
    sh[tid] = local;
    __syncthreads();
    if (tid < 128) atomicAdd(&g_m[slot * HH + col], sh[tid] + sh[tid + 128]);
}

// ---------------- layer-3 GEMV (9 blocks): u += (1/N) * m_slot @ W_slot ----------
__global__ void gemv_kernel(const float* __restrict__ W, const float* __restrict__ root,
                            float* __restrict__ uo) {
    int slot = blockIdx.x;
    int tid = threadIdx.x;             // 128
    const float* Wp = (slot < RR) ? (W + (size_t)slot * HH * HH) : root;
    __shared__ float m[HH];
    m[tid] = g_m[slot * HH + tid];
    __syncthreads();
    float acc = 0.f;
    #pragma unroll 8
    for (int k = 0; k < HH; k++)
        acc += m[k] * Wp[k * HH + tid];
    atomicAdd(&uo[tid], acc * (1.0f / (float)NN));
}

// ---------------- final MLP head (bias of layer-3 folded in here) ----------------
__global__ void fcl_kernel(const float* __restrict__ bias2,
                           const float* __restrict__ fc1w, const float* __restrict__ fc1b,
                           const float* __restrict__ fc2w, const float* __restrict__ fc2b,
                           float* __restrict__ out) {
    __shared__ float h[2 * HH];
    __shared__ float red[HH];
    int tid = threadIdx.x;
    if (tid < 2 * HH) h[tid] = g_u[tid] + bias2[tid & 127];
    __syncthreads();
    if (tid < HH) {
        float y = fc1b[tid];
        for (int k = 0; k < 2 * HH; k++) y += h[k] * fc1w[k * HH + tid];
        y = fmaxf(y, 0.f);
        red[tid] = y * fc2w[tid];
    }
    __syncthreads();
    for (int off = 64; off > 0; off >>= 1) {
        if (tid < off) red[tid] += red[tid + off];
        __syncthreads();
    }
    if (tid == 0) out[0] = red[0] + fc2b[0];
}

// ---------------- host orchestration ----------------
extern "C" void kernel_launch(void* const* d_in, const int* in_sizes, int n_in,
                              void* d_out, int out_size) {
    const float* x1  = (const float*)d_in[0];
    const int*   ei1 = (const int*)d_in[1];
    const int*   et1 = (const int*)d_in[2];
    const float* x2  = (const float*)d_in[3];
    const int*   ei2 = (const int*)d_in[4];
    const int*   et2 = (const int*)d_in[5];
    const float* Wl[3]    = {(const float*)d_in[6],  (const float*)d_in[9],  (const float*)d_in[12]};
    const float* rootl[3] = {(const float*)d_in[7],  (const float*)d_in[10], (const float*)d_in[13]};
    const float* biasl[3] = {(const float*)d_in[8],  (const float*)d_in[11], (const float*)d_in[14]};
    const float* fc1w = (const float*)d_in[15];
    const float* fc1b = (const float*)d_in[16];
    const float* fc2w = (const float*)d_in[17];
    const float* fc2b = (const float*)d_in[18];

    cudaFuncSetAttribute(gemm_kernel, cudaFuncAttributeMaxDynamicSharedMemorySize, GSMEM);

    void *cnt_p, *bsum_p, *m_p, *u_p, *hA_p, *hB_p;
    cudaGetSymbolAddress(&cnt_p, g_cnt);
    cudaGetSymbolAddress(&bsum_p, g_bsum);
    cudaGetSymbolAddress(&m_p, g_m);
    cudaGetSymbolAddress(&u_p, g_u);
    cudaGetSymbolAddress(&hA_p, g_hA);
    cudaGetSymbolAddress(&hB_p, g_hB);
    float* hA = (float*)hA_p;
    float* hB = (float*)hB_p;
    float* u  = (float*)u_p;

    const float* xs[2]  = {x1, x2};
    const int*   eis[2] = {ei1, ei2};
    const int*   ets[2] = {et1, et2};

    int aggBlocks = (NN * RR * 32 + 255) / 256;
    dim3 cmGrid(64, 9);

    cudaMemsetAsync(u_p, 0, 2 * HH * sizeof(float));

    // Kernel launch order (memsets excluded): hist(1) expand(2) scatter(3) agg(4)...
    for (int g = 0; g < 2; g++) {
        cudaMemsetAsync(cnt_p, 0, NN * RR * sizeof(int));
        cudaMemsetAsync(bsum_p, 0, SNB * sizeof(int));
        cudaMemsetAsync(m_p, 0, 9 * HH * sizeof(float));

        hist_kernel<<<(EE + 255) / 256, 256>>>(eis[g], ets[g]);
        expand_kernel<<<SNB, 256>>>();
        scatter_kernel<<<(EE + 255) / 256, 256>>>(eis[g], ets[g]);

        // layer 0: x -> hA
        agg_kernel<<<aggBlocks, 256>>>(xs[g]);
        gemm_kernel<<<GBLK, 256, GSMEM>>>(xs[g], Wl[0], rootl[0], biasl[0], hA);
        // layer 1: hA -> hB
        agg_kernel<<<aggBlocks, 256>>>(hA);
        gemm_kernel<<<GBLK, 256, GSMEM>>>(hA, Wl[1], rootl[1], biasl[1], hB);
        // layer 2 collapsed: only column means are needed
        agg_kernel<<<aggBlocks, 256>>>(hB);
        colmean_kernel<<<cmGrid, 256>>>(hB);
        gemv_kernel<<<9, 128>>>(Wl[2], rootl[2], u + g * HH);
    }

    fcl_kernel<<<1, 256>>>(biasl[2], fc1w, fc1b, fc2w, fc2b, (float*)d_out);
}

// round 10
// speedup vs baseline: 2.6718x; 1.1149x over previous
#include <cuda_runtime.h>
#include <cstdint>

#define NN 50000
#define EE 800000
#define HH 128
#define RR 8
#define SNB 196                       // ceil(NN/256) node blocks

// ---------------- scratch (device globals; no allocation allowed) ----------------
__device__ float g_agg[(size_t)RR * NN * HH];  // [rel][N][128] per-relation neighbor means
__device__ float g_hA[(size_t)NN * HH];
__device__ float g_hB[(size_t)NN * HH];
__device__ int   g_cnt[NN * RR];
__device__ float g_invc[NN * RR];
__device__ int   g_beg[NN * RR];
__device__ int   g_cur[NN * RR];
__device__ int   g_bsum[SNB];         // edges per 256-node block
__device__ int   g_ep[EE];            // src node id, CSR-sorted by (dst, etype)
__device__ float g_wgt[NN * RR];      // w_r[j] = sum over edges (j->n, type r) of invc[n,r]
__device__ float g_m[9 * HH];         // column sums: slots 0..7 weighted, 8 = plain hB sum
__device__ float g_u[2 * HH];         // final per-graph embeddings (pre-bias)

// ---------------- tf32 mma (raw fp32 bits = RZ-truncated tf32) ----------------
__device__ __forceinline__ void mma_tf32(float* c, const unsigned* a, const unsigned* b) {
    asm volatile(
        "mma.sync.aligned.m16n8k8.row.col.f32.tf32.tf32.f32 "
        "{%0,%1,%2,%3}, {%4,%5,%6,%7}, {%8,%9}, {%0,%1,%2,%3};"
        : "+f"(c[0]), "+f"(c[1]), "+f"(c[2]), "+f"(c[3])
        : "r"(a[0]), "r"(a[1]), "r"(a[2]), "r"(a[3]), "r"(b[0]), "r"(b[1]));
}

// ---------------- cp.async helpers ----------------
__device__ __forceinline__ void cp16(uint32_t saddr, const void* gaddr) {
    asm volatile("cp.async.cg.shared.global [%0], [%1], 16;" :: "r"(saddr), "l"(gaddr));
}
__device__ __forceinline__ void cp_commit() {
    asm volatile("cp.async.commit_group;");
}
template <int N>
__device__ __forceinline__ void cp_wait() {
    asm volatile("cp.async.wait_group %0;" :: "n"(N));
}

// ---------------- preprocessing ----------------
__global__ void hist_kernel(const int* __restrict__ ei, const int* __restrict__ et) {
    int e = blockIdx.x * blockDim.x + threadIdx.x;
    if (e < EE) {
        int dst = ei[EE + e];
        int r = et[e];
        atomicAdd(&g_cnt[dst * RR + r], 1);
        atomicAdd(&g_bsum[dst >> 8], 1);
    }
}

// 196 blocks x 256: predecessor prefix over g_bsum + local node scan -> beg/cur/invc
__global__ void expand_kernel() {
    __shared__ int sh[256];
    __shared__ int s_base;
    int b = blockIdx.x;
    int tid = threadIdx.x;

    sh[tid] = (tid < b) ? g_bsum[tid] : 0;
    __syncthreads();
    for (int off = 128; off > 0; off >>= 1) {
        if (tid < off) sh[tid] += sh[tid + off];
        __syncthreads();
    }
    if (tid == 0) s_base = sh[0];
    __syncthreads();

    int i = b * 256 + tid;
    int cv[RR];
    int d = 0;
    if (i < NN) {
        int4 c0 = *(const int4*)&g_cnt[i * RR];
        int4 c1 = *(const int4*)&g_cnt[i * RR + 4];
        cv[0] = c0.x; cv[1] = c0.y; cv[2] = c0.z; cv[3] = c0.w;
        cv[4] = c1.x; cv[5] = c1.y; cv[6] = c1.z; cv[7] = c1.w;
        #pragma unroll
        for (int r = 0; r < RR; r++) d += cv[r];
    }
    sh[tid] = d;
    __syncthreads();
    for (int off = 1; off < 256; off <<= 1) {
        int t = (tid >= off) ? sh[tid - off] : 0;
        __syncthreads();
        sh[tid] += t;
        __syncthreads();
    }
    if (i < NN) {
        int c0 = s_base + sh[tid] - d;
        #pragma unroll
        for (int r = 0; r < RR; r++) {
            g_beg[i * RR + r] = c0;
            g_cur[i * RR + r] = c0;
            g_invc[i * RR + r] = 1.0f / (float)(cv[r] > 0 ? cv[r] : 1);
            c0 += cv[r];
        }
    }
}

__global__ void scatter_kernel(const int* __restrict__ ei, const int* __restrict__ et) {
    int e = blockIdx.x * blockDim.x + threadIdx.x;
    if (e < EE) {
        int comb = ei[EE + e] * RR + et[e];
        int pos = atomicAdd(&g_cur[comb], 1);
        g_ep[pos] = ei[e];
    }
}

// per-src-node relation weights for the collapsed layer-2 column sums
__global__ void wgt_kernel(const int* __restrict__ ei, const int* __restrict__ et) {
    int e = blockIdx.x * blockDim.x + threadIdx.x;
    if (e < EE) {
        int dst = ei[EE + e];
        int r = et[e];
        atomicAdd(&g_wgt[ei[e] * RR + r], g_invc[dst * RR + r]);
    }
}

// ---------------- aggregation: warp per (rel,node); writes g_agg[rel][N][128] -----
__global__ void agg_kernel(const float* __restrict__ X) {
    int gw = (blockIdx.x * blockDim.x + threadIdx.x) >> 5;
    int lane = threadIdx.x & 31;
    if (gw >= NN * RR) return;
    int rel = gw / NN;
    int node = gw - rel * NN;

    int comb = node * RR + rel;
    int b = g_beg[comb];
    int c = g_cnt[comb];
    float4 a = make_float4(0.f, 0.f, 0.f, 0.f);
    for (int e = b; e < b + c; e++) {
        int src = g_ep[e];
        float4 v = ((const float4*)(X + (size_t)src * HH))[lane];
        a.x += v.x; a.y += v.y; a.z += v.z; a.w += v.w;
    }
    float w = g_invc[comb];
    a.x *= w; a.y *= w; a.z *= w; a.w *= w;
    ((float4*)(g_agg + ((size_t)rel * NN + node) * HH))[lane] = a;
}

// ---------------- tf32 tensor-core GEMM, cp.async double-buffered -----------------
#define BM 128
#define GBLK ((NN + BM - 1) / BM)
#define APAD 36
#define BPAD 136
#define ASZ (128 * APAD)
#define BSZ (32 * BPAD)
#define GSMEM (2 * (ASZ + BSZ) * 4)

__global__ __launch_bounds__(256) void gemm_kernel(
    const float* __restrict__ X, const float* __restrict__ W,
    const float* __restrict__ root, const float* __restrict__ bias,
    float* __restrict__ out)
{
    extern __shared__ float smem[];
    uint32_t sbase = (uint32_t)__cvta_generic_to_shared(smem);

    int tid  = threadIdx.x;
    int warp = tid >> 5;
    int lane = tid & 31;
    int gID  = lane >> 2;
    int tig  = lane & 3;
    int wrow = (warp & 3) * 32;
    int wcol = (warp >> 2) * 64;
    int m0   = blockIdx.x * BM;

    int arow = tid >> 3, aq = (tid & 7) * 4;
    int bkr  = tid >> 5, bnq = (tid & 31) * 4;

    float c[2][8][4];
    #pragma unroll
    for (int mt = 0; mt < 2; mt++)
        #pragma unroll
        for (int nt = 0; nt < 8; nt++)
            #pragma unroll
            for (int q = 0; q < 4; q++) c[mt][nt][q] = 0.f;

    auto stage = [&](int ch, int buf) {
        int rel = ch >> 2, kc = ch & 3;
        const float* Wp   = (rel < RR) ? (W + (size_t)rel * HH * HH) : root;
        const float* Asrc = (rel < RR) ? (g_agg + (size_t)rel * NN * HH) : X;
        uint32_t abase = sbase + (uint32_t)(buf * ASZ) * 4;
        uint32_t bbase = sbase + (uint32_t)(2 * ASZ + buf * BSZ) * 4;
        #pragma unroll
        for (int it = 0; it < 4; it++) {
            int row = arow + it * 32;
            int gm  = m0 + row; if (gm > NN - 1) gm = NN - 1;
            cp16(abase + (uint32_t)(row * APAD + aq) * 4,
                 Asrc + (size_t)gm * HH + kc * 32 + aq);
            int kr = bkr + it * 8;
            cp16(bbase + (uint32_t)(kr * BPAD + bnq) * 4,
                 Wp + (size_t)(kc * 32 + kr) * HH + bnq);
        }
        cp_commit();
    };

    stage(0, 0);

    for (int ch = 0; ch < 36; ch++) {
        int buf = ch & 1;
        if (ch < 35) { stage(ch + 1, buf ^ 1); cp_wait<1>(); }
        else         { cp_wait<0>(); }
        __syncthreads();

        const float* As = smem + buf * ASZ;
        const float* Bs = smem + 2 * ASZ + buf * BSZ;

        #pragma unroll
        for (int ks = 0; ks < 4; ks++) {
            int kb = ks * 8;
            unsigned b[8][2];
            #pragma unroll
            for (int nt = 0; nt < 8; nt++) {
                int col = wcol + nt * 8 + gID;
                b[nt][0] = __float_as_uint(Bs[(kb + tig) * BPAD + col]);
                b[nt][1] = __float_as_uint(Bs[(kb + tig + 4) * BPAD + col]);
            }
            unsigned a[2][4];
            #pragma unroll
            for (int mt = 0; mt < 2; mt++) {
                int r = wrow + mt * 16 + gID;
                a[mt][0] = __float_as_uint(As[r * APAD + kb + tig]);
                a[mt][1] = __float_as_uint(As[(r + 8) * APAD + kb + tig]);
                a[mt][2] = __float_as_uint(As[r * APAD + kb + tig + 4]);
                a[mt][3] = __float_as_uint(As[(r + 8) * APAD + kb + tig + 4]);
            }
            #pragma unroll
            for (int mt = 0; mt < 2; mt++)
                #pragma unroll
                for (int nt = 0; nt < 8; nt++)
                    mma_tf32(c[mt][nt], a[mt], b[nt]);
        }
        __syncthreads();
    }

    #pragma unroll
    for (int mt = 0; mt < 2; mt++) {
        int r0 = m0 + wrow + mt * 16 + gID;
        int r1 = r0 + 8;
        #pragma unroll
        for (int nt = 0; nt < 8; nt++) {
            int col = wcol + nt * 8 + 2 * tig;
            float b0 = bias[col], b1 = bias[col + 1];
            float v0 = fmaxf(c[mt][nt][0] + b0, 0.f);
            float v1 = fmaxf(c[mt][nt][1] + b1, 0.f);
            float v2 = fmaxf(c[mt][nt][2] + b0, 0.f);
            float v3 = fmaxf(c[mt][nt][3] + b1, 0.f);
            if (r0 < NN) *(float2*)(out + (size_t)r0 * HH + col) = make_float2(v0, v1);
            if (r1 < NN) *(float2*)(out + (size_t)r1 * HH + col) = make_float2(v2, v3);
        }
    }
}

// ---------------- collapsed layer-2: all 9 column sums in ONE pass over hB --------
// g_m[r][c] = sum_j w_r[j]*hB[j][c] (r<8);  g_m[8][c] = sum_j hB[j][c]
#define WS_BLOCKS 148
__global__ void wsum_kernel(const float* __restrict__ hB) {
    __shared__ float sw[256 * RR];
    int tid = threadIdx.x;             // 128 threads = columns
    int rowsPer = (NN + gridDim.x - 1) / gridDim.x;
    int r0 = blockIdx.x * rowsPer;
    int r1 = min(NN, r0 + rowsPer);

    float acc[9];
    #pragma unroll
    for (int s = 0; s < 9; s++) acc[s] = 0.f;

    for (int base = r0; base < r1; base += 256) {
        int nrows = min(256, r1 - base);
        // stage weights for this chunk: nrows*8 floats
        for (int idx = tid * 4; idx < nrows * RR; idx += 128 * 4)
            *(float4*)&sw[idx] = *(const float4*)&g_wgt[base * RR + idx];
        __syncthreads();
        for (int j = 0; j < nrows; j++) {
            float v = hB[(size_t)(base + j) * HH + tid];
            acc[8] += v;
            #pragma unroll
            for (int r = 0; r < RR; r++) acc[r] += sw[j * RR + r] * v;
        }
        __syncthreads();
    }
    #pragma unroll
    for (int s = 0; s < 9; s++) atomicAdd(&g_m[s * HH + tid], acc[s]);
}

// ---------------- layer-3 GEMV (9 blocks): u += (1/N) * m_slot @ W_slot ----------
__global__ void gemv_kernel(const float* __restrict__ W, const float* __restrict__ root,
                            float* __restrict__ uo) {
    int slot = blockIdx.x;
    int tid = threadIdx.x;             // 128
    const float* Wp = (slot < RR) ? (W + (size_t)slot * HH * HH) : root;
    __shared__ float m[HH];
    m[tid] = g_m[slot * HH + tid];
    __syncthreads();
    float acc = 0.f;
    #pragma unroll 8
    for (int k = 0; k < HH; k++)
        acc += m[k] * Wp[k * HH + tid];
    atomicAdd(&uo[tid], acc * (1.0f / (float)NN));
}

// ---------------- final MLP head (bias of layer-3 folded in here) ----------------
__global__ void fcl_kernel(const float* __restrict__ bias2,
                           const float* __restrict__ fc1w, const float* __restrict__ fc1b,
                           const float* __restrict__ fc2w, const float* __restrict__ fc2b,
                           float* __restrict__ out) {
    __shared__ float h[2 * HH];
    __shared__ float red[HH];
    int tid = threadIdx.x;
    if (tid < 2 * HH) h[tid] = g_u[tid] + bias2[tid & 127];
    __syncthreads();
    if (tid < HH) {
        float y = fc1b[tid];
        for (int k = 0; k < 2 * HH; k++) y += h[k] * fc1w[k * HH + tid];
        y = fmaxf(y, 0.f);
        red[tid] = y * fc2w[tid];
    }
    __syncthreads();
    for (int off = 64; off > 0; off >>= 1) {
        if (tid < off) red[tid] += red[tid + off];
        __syncthreads();
    }
    if (tid == 0) out[0] = red[0] + fc2b[0];
}

// ---------------- host orchestration ----------------
extern "C" void kernel_launch(void* const* d_in, const int* in_sizes, int n_in,
                              void* d_out, int out_size) {
    const float* x1  = (const float*)d_in[0];
    const int*   ei1 = (const int*)d_in[1];
    const int*   et1 = (const int*)d_in[2];
    const float* x2  = (const float*)d_in[3];
    const int*   ei2 = (const int*)d_in[4];
    const int*   et2 = (const int*)d_in[5];
    const float* Wl[3]    = {(const float*)d_in[6],  (const float*)d_in[9],  (const float*)d_in[12]};
    const float* rootl[3] = {(const float*)d_in[7],  (const float*)d_in[10], (const float*)d_in[13]};
    const float* biasl[3] = {(const float*)d_in[8],  (const float*)d_in[11], (const float*)d_in[14]};
    const float* fc1w = (const float*)d_in[15];
    const float* fc1b = (const float*)d_in[16];
    const float* fc2w = (const float*)d_in[17];
    const float* fc2b = (const float*)d_in[18];

    cudaFuncSetAttribute(gemm_kernel, cudaFuncAttributeMaxDynamicSharedMemorySize, GSMEM);

    void *cnt_p, *bsum_p, *wgt_p, *m_p, *u_p, *hA_p, *hB_p;
    cudaGetSymbolAddress(&cnt_p, g_cnt);
    cudaGetSymbolAddress(&bsum_p, g_bsum);
    cudaGetSymbolAddress(&wgt_p, g_wgt);
    cudaGetSymbolAddress(&m_p, g_m);
    cudaGetSymbolAddress(&u_p, g_u);
    cudaGetSymbolAddress(&hA_p, g_hA);
    cudaGetSymbolAddress(&hB_p, g_hB);
    float* hA = (float*)hA_p;
    float* hB = (float*)hB_p;
    float* u  = (float*)u_p;

    const float* xs[2]  = {x1, x2};
    const int*   eis[2] = {ei1, ei2};
    const int*   ets[2] = {et1, et2};

    int aggBlocks = (NN * RR * 32 + 255) / 256;
    int eBlocks   = (EE + 255) / 256;

    cudaMemsetAsync(u_p, 0, 2 * HH * sizeof(float));

    for (int g = 0; g < 2; g++) {
        cudaMemsetAsync(cnt_p, 0, NN * RR * sizeof(int));
        cudaMemsetAsync(bsum_p, 0, SNB * sizeof(int));
        cudaMemsetAsync(wgt_p, 0, NN * RR * sizeof(float));
        cudaMemsetAsync(m_p, 0, 9 * HH * sizeof(float));

        hist_kernel<<<eBlocks, 256>>>(eis[g], ets[g]);
        expand_kernel<<<SNB, 256>>>();
        scatter_kernel<<<eBlocks, 256>>>(eis[g], ets[g]);
        wgt_kernel<<<eBlocks, 256>>>(eis[g], ets[g]);

        // layer 0: x -> hA
        agg_kernel<<<aggBlocks, 256>>>(xs[g]);
        gemm_kernel<<<GBLK, 256, GSMEM>>>(xs[g], Wl[0], rootl[0], biasl[0], hA);
        // layer 1: hA -> hB
        agg_kernel<<<aggBlocks, 256>>>(hA);
        gemm_kernel<<<GBLK, 256, GSMEM>>>(hA, Wl[1], rootl[1], biasl[1], hB);
        // layers 2+3 collapsed: weighted column sums of hB, then GEMV
        wsum_kernel<<<WS_BLOCKS, 128>>>(hB);
        gemv_kernel<<<9, 128>>>(Wl[2], rootl[2], u + g * HH);
    }

    fcl_kernel<<<1, 256>>>(biasl[2], fc1w, fc1b, fc2w, fc2b, (float*)d_out);
}